// round 11
// baseline (speedup 1.0000x reference)
#include <cuda_runtime.h>
#include <math.h>

#define NB   16
#define CIN  256
#define MIP  64
#define SEQ  192

// ---- scratch (device globals; no allocation allowed) ----
__device__ float g_y0[NB * CIN * SEQ];    // pooled + concat (b, 256, 192)
__device__ float g_ah[NB * CIN * 96];     // sigmoid attention (h)
__device__ float g_aw[NB * CIN * 96];     // sigmoid attention (w)

// ---------------- helpers ----------------
__device__ __forceinline__ void cp_async4(void* smem_dst, const void* gmem_src) {
    unsigned s = (unsigned)__cvta_generic_to_shared(smem_dst);
    asm volatile("cp.async.ca.shared.global [%0], [%1], 4;" :: "r"(s), "l"(gmem_src));
}
__device__ __forceinline__ void cp_async16(void* smem_dst, const void* gmem_src) {
    unsigned s = (unsigned)__cvta_generic_to_shared(smem_dst);
    asm volatile("cp.async.cg.shared.global [%0], [%1], 16;" :: "r"(s), "l"(gmem_src));
}
__device__ __forceinline__ void cp_commit() {
    asm volatile("cp.async.commit_group;");
}
__device__ __forceinline__ void cp_wait0() {
    asm volatile("cp.async.wait_group 0;" ::: "memory");
}
__device__ __forceinline__ unsigned long long pack2(float a, float b) {
    unsigned long long r;
    asm("mov.b64 %0, {%1, %2};" : "=l"(r) : "f"(a), "f"(b));
    return r;
}
__device__ __forceinline__ unsigned long long ffma2(unsigned long long a,
                                                    unsigned long long b,
                                                    unsigned long long c) {
    unsigned long long d;
    asm("fma.rn.f32x2 %0, %1, %2, %3;" : "=l"(d) : "l"(a), "l"(b), "l"(c));
    return d;
}
__device__ __forceinline__ void unpack2(unsigned long long v, float& lo, float& hi) {
    asm("mov.b64 {%0, %1}, %2;" : "=f"(lo), "=f"(hi) : "l"(v));
}

// ===================== K1: row & col means, TWO planes per block =====================
__global__ void k_means(const float* __restrict__ x) {
    __shared__ float  srp[96 * 25];
    __shared__ float4 sc4[12 * 24];
    const int bc0 = blockIdx.x * 2;
    const int tid = threadIdx.x;
    const int c4  = tid % 24;
    const int rg  = tid / 24;
    const float4* xp0 = (const float4*)(x + (size_t)bc0 * 9216);
    const float4* xp1 = xp0 + 2304;

    float4 v[8], u[8];
    #pragma unroll
    for (int j = 0; j < 8; j++) v[j] = __ldg(&xp0[(8 * rg + j) * 24 + c4]);
    #pragma unroll
    for (int j = 0; j < 8; j++) u[j] = __ldg(&xp1[(8 * rg + j) * 24 + c4]);

    {
        float4 ca = make_float4(0.f, 0.f, 0.f, 0.f);
        #pragma unroll
        for (int j = 0; j < 8; j++) {
            ca.x += v[j].x; ca.y += v[j].y; ca.z += v[j].z; ca.w += v[j].w;
            srp[(8 * rg + j) * 25 + c4] = (v[j].x + v[j].y) + (v[j].z + v[j].w);
        }
        sc4[rg * 24 + c4] = ca;
    }
    __syncthreads();
    if (tid < 96) {
        const float* rp = &srp[tid * 25];
        float s0 = 0.f, s1 = 0.f, s2 = 0.f, s3 = 0.f;
        #pragma unroll
        for (int j = 0; j < 24; j += 4) {
            s0 += rp[j]; s1 += rp[j + 1]; s2 += rp[j + 2]; s3 += rp[j + 3];
        }
        g_y0[(size_t)bc0 * SEQ + tid] = ((s0 + s1) + (s2 + s3)) * (1.f / 96.f);
    } else if (tid < 192) {
        int c = tid - 96;
        const float* scf = (const float*)sc4;
        float s0 = 0.f, s1 = 0.f, s2 = 0.f, s3 = 0.f;
        #pragma unroll
        for (int r = 0; r < 12; r += 4) {
            s0 += scf[(r + 0) * 96 + c];
            s1 += scf[(r + 1) * 96 + c];
            s2 += scf[(r + 2) * 96 + c];
            s3 += scf[(r + 3) * 96 + c];
        }
        g_y0[(size_t)bc0 * SEQ + 96 + c] = ((s0 + s1) + (s2 + s3)) * (1.f / 96.f);
    }
    __syncthreads();

    {
        float4 ca = make_float4(0.f, 0.f, 0.f, 0.f);
        #pragma unroll
        for (int j = 0; j < 8; j++) {
            ca.x += u[j].x; ca.y += u[j].y; ca.z += u[j].z; ca.w += u[j].w;
            srp[(8 * rg + j) * 25 + c4] = (u[j].x + u[j].y) + (u[j].z + u[j].w);
        }
        sc4[rg * 24 + c4] = ca;
    }
    __syncthreads();
    if (tid < 96) {
        const float* rp = &srp[tid * 25];
        float s0 = 0.f, s1 = 0.f, s2 = 0.f, s3 = 0.f;
        #pragma unroll
        for (int j = 0; j < 24; j += 4) {
            s0 += rp[j]; s1 += rp[j + 1]; s2 += rp[j + 2]; s3 += rp[j + 3];
        }
        g_y0[(size_t)(bc0 + 1) * SEQ + tid] = ((s0 + s1) + (s2 + s3)) * (1.f / 96.f);
    } else if (tid < 192) {
        int c = tid - 96;
        const float* scf = (const float*)sc4;
        float s0 = 0.f, s1 = 0.f, s2 = 0.f, s3 = 0.f;
        #pragma unroll
        for (int r = 0; r < 12; r += 4) {
            s0 += scf[(r + 0) * 96 + c];
            s1 += scf[(r + 1) * 96 + c];
            s2 += scf[(r + 2) * 96 + c];
            s3 += scf[(r + 3) * 96 + c];
        }
        g_y0[(size_t)(bc0 + 1) * SEQ + 96 + c] = ((s0 + s1) + (s2 + s3)) * (1.f / 96.f);
    }
}

// ========== K2 (merged middle): conv1 + inv1 + BN + hswish + inv2 + conv2 + sigmoid ==========
// grid = NB*2*4 = 128 (b, half, chunk of 24), block = 512, 174KB dyn smem.
// Each block recomputes its y2 window (30 pos, halo) locally: no g_y2 round trip.
#define MID_SMEM_FLOATS 43504
__global__ void __launch_bounds__(512, 1)
k_mid(const float* __restrict__ wc1, const float* __restrict__ bc1,
      const float* __restrict__ i1w1, const float* __restrict__ i1b1,
      const float* __restrict__ i1w2, const float* __restrict__ i1b2,
      const float* __restrict__ bng, const float* __restrict__ bnb,
      const float* __restrict__ bnm, const float* __restrict__ bnv,
      const float* __restrict__ w1h, const float* __restrict__ b1h,
      const float* __restrict__ w2h, const float* __restrict__ b2h,
      const float* __restrict__ wch, const float* __restrict__ bch,
      const float* __restrict__ w1w, const float* __restrict__ b1w,
      const float* __restrict__ w2w, const float* __restrict__ b2w,
      const float* __restrict__ wcw, const float* __restrict__ bcw) {
    extern __shared__ float dyn[];
    float* sbig  = dyn;                 // 16640: w_c1 (64x pad257), later wc (256x pad65)
    float* ys    = sbig  + 16640;       // 9216 (256 x 36)
    float* y1s   = ys    + 9216;        // 2368 (64 x pad37)
    float* si1w1 = y1s   + 2368;        // 1024
    float* si1b1 = si1w1 + 1024;        // 16
    float* si1w2 = si1b1 + 16;          // 3136
    float* si1b2 = si1w2 + 3136;        // 196
    float* sbc1  = si1b2 + 196;         // 64
    float* sbn   = sbc1  + 64;          // 256
    float* shw1  = sbn   + 256;         // 1024
    float* shb1  = shw1  + 1024;        // 16
    float* shw2  = shb1  + 16;          // 3136
    float* shb2  = shw2  + 3136;        // 196
    float* sbc   = shb2  + 196;         // 256
    float* st    = sbc   + 256;         // 480 (16 x 30)
    float* sg    = st    + 480;         // 840 (28 x 30)
    float* sy    = sg    + 840;         // 2048 (64 x 32)
    float* st2   = sy    + 2048;        // 384
    float* sg2   = st2   + 384;         // 672
    float* sz    = sg2   + 672;         // 1536

    const int bid  = blockIdx.x;
    const int b    = bid >> 3;
    const int rest = bid & 7;
    const int half = rest >> 2;
    const int p0   = (rest & 3) * 24;
    const int seq0 = 96 * half + p0 - 6;   // y1/y0 window base in 192-seq
    const int tid  = threadIdx.x;

    const float* w1 = half ? w1w : w1h;
    const float* b1 = half ? b1w : b1h;
    const float* w2 = half ? w2w : w2h;
    const float* b2 = half ? b2w : b2h;
    const float* wc = half ? wcw : wch;
    const float* bc = half ? bcw : bch;
    float* outbuf   = half ? g_aw : g_ah;

    // ---- group 0: w_c1 + inv1 weights + BN + half inv weights ----
    for (int i = tid; i < 64 * 256; i += 512)
        cp_async4(&sbig[(i >> 8) * 257 + (i & 255)], wc1 + i);
    for (int i = tid; i < 256; i += 512) cp_async16(&si1w1[i * 4], i1w1 + i * 4);
    if (tid < 16)  cp_async4(&si1b1[tid], i1b1 + tid);
    for (int i = tid; i < 784; i += 512) cp_async16(&si1w2[i * 4], i1w2 + i * 4);
    if (tid < 196) cp_async4(&si1b2[tid], i1b2 + tid);
    if (tid < 64)  cp_async4(&sbc1[tid], bc1 + tid);
    if (tid < 64)        cp_async4(&sbn[tid], bng + tid);
    else if (tid < 128)  cp_async4(&sbn[tid], bnb + tid - 64);
    else if (tid < 192)  cp_async4(&sbn[tid], bnm + tid - 128);
    else if (tid < 256)  cp_async4(&sbn[tid], bnv + tid - 192);
    for (int i = tid; i < 256; i += 512) cp_async16(&shw1[i * 4], w1 + i * 4);
    if (tid < 16)  cp_async4(&shb1[tid], b1 + tid);
    for (int i = tid; i < 784; i += 512) cp_async16(&shw2[i * 4], w2 + i * 4);
    if (tid < 196) cp_async4(&shb2[tid], b2 + tid);
    cp_commit();

    // ---- y0 tile (256 x 36), regular LDG ----
    for (int i = tid; i < CIN * 36; i += 512) {
        int c = i / 36, sp = i % 36;
        int gp = seq0 + sp;
        ys[i] = (gp >= 0 && gp < SEQ) ? g_y0[((size_t)b * CIN + c) * SEQ + gp] : 0.f;
    }
    cp_wait0();
    __syncthreads();

    // ---- conv1: y1[o][sp], sp 0..31 (f32x2) + tail sp 32..35 ----
    {
        const int o  = tid & 63;
        const int pg = tid >> 6;
        unsigned long long a0 = 0ull, a1 = 0ull;
        #pragma unroll 8
        for (int c = 0; c < CIN; c++) {
            float wv = sbig[o * 257 + c];
            unsigned long long wp = pack2(wv, wv);
            longlong2 y = *(const longlong2*)&ys[c * 36 + pg * 4];
            a0 = ffma2(wp, (unsigned long long)y.x, a0);
            a1 = ffma2(wp, (unsigned long long)y.y, a1);
        }
        float v0, v1, v2, v3;
        unpack2(a0, v0, v1); unpack2(a1, v2, v3);
        float bo = sbc1[o];
        int spb = pg * 4;
        float* dst = &y1s[o * 37 + spb];
        int g0 = seq0 + spb;
        dst[0] = (g0 + 0 >= 0 && g0 + 0 < SEQ) ? v0 + bo : 0.f;
        dst[1] = (g0 + 1 >= 0 && g0 + 1 < SEQ) ? v1 + bo : 0.f;
        dst[2] = (g0 + 2 >= 0 && g0 + 2 < SEQ) ? v2 + bo : 0.f;
        dst[3] = (g0 + 3 >= 0 && g0 + 3 < SEQ) ? v3 + bo : 0.f;

        if (tid < 256) {
            int o2 = tid & 63, sp = 32 + (tid >> 6);
            float acc = 0.f;
            #pragma unroll 8
            for (int c = 0; c < CIN; c++) acc += sbig[o2 * 257 + c] * ys[c * 36 + sp];
            int gq = seq0 + sp;
            y1s[o2 * 37 + sp] = (gq >= 0 && gq < SEQ) ? acc + sbc1[o2] : 0.f;
        }
    }
    __syncthreads();

    // ---- group 1: conv2 weights into sbig (overwrite) + bias ----
    for (int i = tid; i < CIN * MIP; i += 512)
        cp_async4(&sbig[(i >> 6) * 65 + (i & 63)], wc + i);
    if (tid < 256) cp_async4(&sbc[tid], bc + tid);
    cp_commit();

    // ---- inv1 t-phase: t[r][ws], 16 x 30 ----
    if (tid < 480) {
        int r = tid / 30, ws = tid % 30;
        float acc = si1b1[r];
        const float* wr = &si1w1[r * 64];
        #pragma unroll 8
        for (int c = 0; c < MIP; c++) acc += wr[c] * y1s[c * 37 + ws + 3];
        st[r * 30 + ws] = acc;
    }
    __syncthreads();

    // ---- inv1 wgt rows: 28 x 30 ----
    for (int i = tid; i < 840; i += 512) {
        int r = i / 30, ws = i % 30;
        int g = r / 7, kh = r % 7;
        int row = g * 49 + kh * 7 + 3;
        float acc = si1b2[row];
        const float* wr = &si1w2[row * 16];
        #pragma unroll
        for (int c = 0; c < 16; c++) acc += wr[c] * st[c * 30 + ws];
        sg[i] = acc;
    }
    __syncthreads();

    // ---- inv1 + BN + hswish -> sy (64 x 32, zero outside half) ----
    for (int i = tid; i < 2048; i += 512) {
        int c = i >> 5, ws = i & 31;
        float out = 0.f;
        if (ws < 30) {
            int g = c >> 4;
            float acc = 0.f;
            #pragma unroll
            for (int kh = 0; kh < 7; kh++)
                acc += sg[(g * 7 + kh) * 30 + ws] * y1s[c * 37 + ws + kh];
            float sc = sbn[c] * rsqrtf(sbn[192 + c] + 1e-5f);
            float v  = (acc - sbn[128 + c]) * sc + sbn[64 + c];
            float hs = v * fminf(fmaxf(v + 3.f, 0.f), 6.f) * (1.f / 6.f);
            int hp = p0 - 3 + ws;
            out = (hp >= 0 && hp < 96) ? hs : 0.f;
        }
        sy[i] = out;
    }
    __syncthreads();

    // ---- inv2 t-phase: 16 x 24 ----
    if (tid < 384) {
        int r = tid / 24, p = tid % 24;
        float acc = shb1[r];
        const float* wr = &shw1[r * 64];
        #pragma unroll 8
        for (int c = 0; c < MIP; c++) acc += wr[c] * sy[c * 32 + 3 + p];
        st2[r * 24 + p] = acc;
    }
    __syncthreads();

    // ---- inv2 wgt rows: 28 x 24 (half-dependent rows) ----
    for (int i = tid; i < 672; i += 512) {
        int r = i / 24, p = i % 24;
        int g = r / 7, kh = r % 7;
        int row = half ? (g * 49 + 21 + kh) : (g * 49 + kh * 7 + 3);
        float acc = shb2[row];
        const float* wr = &shw2[row * 16];
        #pragma unroll
        for (int c = 0; c < 16; c++) acc += wr[c] * st2[c * 24 + p];
        sg2[i] = acc;
    }
    __syncthreads();

    // ---- inv2: 64 x 24 -> sz ----
    for (int i = tid; i < MIP * 24; i += 512) {
        int c = i / 24, p = i % 24;
        int g = c >> 4;
        float acc = 0.f;
        #pragma unroll
        for (int kh = 0; kh < 7; kh++)
            acc += sg2[(g * 7 + kh) * 24 + p] * sy[c * 32 + p + kh];
        sz[c * 24 + p] = acc;
    }
    cp_wait0();
    __syncthreads();

    // ---- conv 64 -> 256 + sigmoid ----
    {
        const int og = tid >> 1;
        const int q  = tid & 1;
        unsigned long long acc[6];
        #pragma unroll
        for (int k = 0; k < 6; k++) acc[k] = 0ull;
        #pragma unroll 4
        for (int c = 0; c < MIP; c++) {
            float wv = sbig[og * 65 + c];
            unsigned long long wp = pack2(wv, wv);
            const longlong2* zp = (const longlong2*)&sz[c * 24 + q * 12];
            longlong2 za = zp[0];
            longlong2 zb = zp[1];
            longlong2 zc = zp[2];
            acc[0] = ffma2(wp, (unsigned long long)za.x, acc[0]);
            acc[1] = ffma2(wp, (unsigned long long)za.y, acc[1]);
            acc[2] = ffma2(wp, (unsigned long long)zb.x, acc[2]);
            acc[3] = ffma2(wp, (unsigned long long)zb.y, acc[3]);
            acc[4] = ffma2(wp, (unsigned long long)zc.x, acc[4]);
            acc[5] = ffma2(wp, (unsigned long long)zc.y, acc[5]);
        }
        float bo = sbc[og];
        float* op = outbuf + ((size_t)b * CIN + og) * 96 + p0 + q * 12;
        #pragma unroll
        for (int k = 0; k < 6; k++) {
            float lo, hi;
            unpack2(acc[k], lo, hi);
            op[2 * k]     = 1.f / (1.f + __expf(-(lo + bo)));
            op[2 * k + 1] = 1.f / (1.f + __expf(-(hi + bo)));
        }
    }
}

// ===================== K3: out = x * a_h * a_w, 2 float4 per thread =====================
__global__ void k_final(const float4* __restrict__ x, float4* __restrict__ out) {
    int bc    = 4095 - (int)blockIdx.y;
    int chunk = 5 - (int)blockIdx.x;
    int t2 = chunk * 192 + threadIdx.x;
    int row = t2 / 12;
    int jf  = (t2 % 12) * 2;

    float h = __ldg(g_ah + (size_t)bc * 96 + row);
    const float4* aw4 = (const float4*)g_aw;
    float4 w0 = __ldg(aw4 + (size_t)bc * 24 + jf);
    float4 w1 = __ldg(aw4 + (size_t)bc * 24 + jf + 1);

    size_t idx = (size_t)bc * 2304 + 2 * t2;
    float4 x0 = __ldg(x + idx);
    float4 x1 = __ldg(x + idx + 1);

    float4 r0, r1;
    r0.x = x0.x * h * w0.x; r0.y = x0.y * h * w0.y;
    r0.z = x0.z * h * w0.z; r0.w = x0.w * h * w0.w;
    r1.x = x1.x * h * w1.x; r1.y = x1.y * h * w1.y;
    r1.z = x1.z * h * w1.z; r1.w = x1.w * h * w1.w;
    __stcs(out + idx,     r0);
    __stcs(out + idx + 1, r1);
}

// ===================== launch =====================
extern "C" void kernel_launch(void* const* d_in, const int* in_sizes, int n_in,
                              void* d_out, int out_size) {
    const float* x     = (const float*)d_in[0];
    const float* w_c1  = (const float*)d_in[1];
    const float* b_c1  = (const float*)d_in[2];
    const float* i1w1  = (const float*)d_in[3];
    const float* i1b1  = (const float*)d_in[4];
    const float* i1w2  = (const float*)d_in[5];
    const float* i1b2  = (const float*)d_in[6];
    const float* bng   = (const float*)d_in[7];
    const float* bnb   = (const float*)d_in[8];
    const float* bnm   = (const float*)d_in[9];
    const float* bnv   = (const float*)d_in[10];
    const float* ihw1  = (const float*)d_in[11];
    const float* ihb1  = (const float*)d_in[12];
    const float* ihw2  = (const float*)d_in[13];
    const float* ihb2  = (const float*)d_in[14];
    const float* w_h   = (const float*)d_in[15];
    const float* b_h   = (const float*)d_in[16];
    const float* iww1  = (const float*)d_in[17];
    const float* iwb1  = (const float*)d_in[18];
    const float* iww2  = (const float*)d_in[19];
    const float* iwb2  = (const float*)d_in[20];
    const float* w_w   = (const float*)d_in[21];
    const float* b_w   = (const float*)d_in[22];

    cudaFuncSetAttribute(k_mid, cudaFuncAttributeMaxDynamicSharedMemorySize,
                         MID_SMEM_FLOATS * 4);

    k_means<<<NB * CIN / 2, 288>>>(x);
    k_mid<<<NB * 2 * 4, 512, MID_SMEM_FLOATS * 4>>>(
        w_c1, b_c1, i1w1, i1b1, i1w2, i1b2, bng, bnb, bnm, bnv,
        ihw1, ihb1, ihw2, ihb2, w_h, b_h,
        iww1, iwb1, iww2, iwb2, w_w, b_w);
    k_final<<<dim3(6, NB * CIN), 192>>>((const float4*)x, (float4*)d_out);
}